// round 15
// baseline (speedup 1.0000x reference)
#include <cuda_runtime.h>
#include <cuda_bf16.h>
#include <math.h>

#define N_NODES 12288
#define N_EDGES 196608
#define F_IN    1433
#define H1      32
#define H2      16
#define NCLS    7

#define NKS     90              // k16 steps total (90*16 = 1440 >= 1433)
#define SPLITS  4               // K-split across warp pairs
#define SPS     23              // ksteps per split (ceil(90/4))

// ---- scratch (static device globals; no allocation allowed) ----
__device__ float g_xw  [N_NODES * H1];
__device__ float g_h   [N_NODES * H1];
__device__ float g_agg1[N_NODES * H1];
__device__ float g_agg2[N_NODES * H1];
__device__ float g_deg [N_NODES];
__device__ float g_cnt [N_NODES];
__device__ int   g_row [N_EDGES];
__device__ int   g_col [N_EDGES];
// B fragment tables, fragment-ready layout: uint4 index = (kp*8 + g), kp = 8s+tp
__device__ uint4 g_bfhi[NKS * 8 * 8];    // 92 KB
__device__ uint4 g_bflo[NKS * 8 * 8];    // 92 KB

__device__ __forceinline__ void red4(float* p, float a, float b, float c, float d) {
    asm volatile("red.global.add.v4.f32 [%0], {%1, %2, %3, %4};"
                 :: "l"(p), "f"(a), "f"(b), "f"(c), "f"(d) : "memory");
}

#define MMA16816(c, a0, a1, a2, a3, b0, b1) \
    asm volatile("mma.sync.aligned.m16n8k16.row.col.f32.bf16.bf16.f32 " \
        "{%0,%1,%2,%3}, {%4,%5,%6,%7}, {%8,%9}, {%0,%1,%2,%3};" \
        : "+f"((c)[0]), "+f"((c)[1]), "+f"((c)[2]), "+f"((c)[3]) \
        : "r"(a0), "r"(a1), "r"(a2), "r"(a3), "r"(b0), "r"(b1))

__device__ __forceinline__ unsigned bits2(__nv_bfloat162 v) {
    unsigned u; memcpy(&u, &v, 4); return u;
}

// ---- launch 1: zero agg1, init deg/cnt ----
__global__ void k_init_a() {
    int i = blockIdx.x * blockDim.x + threadIdx.x;
    if (i < N_NODES * H1) g_agg1[i] = 0.f;
    if (i < N_NODES) { g_deg[i] = 1.f; g_cnt[i] = 0.f; }
}

// ---- launch 2: pack W1 into bf16 hi/lo B-fragment tables ----
// thread -> (kp, col): k = 2*kp; g = col&7, j = col>>3; word (kp*8+g)*4 + j
__global__ void k_wpack(const float* __restrict__ W1) {
    int i = blockIdx.x * blockDim.x + threadIdx.x;
    if (i >= NKS * 8 * 32) return;
    int kp  = i >> 5;
    int col = i & 31;
    int k   = 2 * kp;
    float f0 = (k     < F_IN) ? __ldg(W1 + (size_t)k * H1 + col)       : 0.f;
    float f1 = (k + 1 < F_IN) ? __ldg(W1 + (size_t)(k + 1) * H1 + col) : 0.f;
    __nv_bfloat162 h = __float22bfloat162_rn(make_float2(f0, f1));
    __nv_bfloat162 l = __float22bfloat162_rn(
        make_float2(f0 - __bfloat162float(h.x), f1 - __bfloat162float(h.y)));
    int g = col & 7, j = col >> 3;
    int w = (kp * 8 + g) * 4 + j;
    ((unsigned*)g_bfhi)[w] = bits2(h);
    ((unsigned*)g_bflo)[w] = bits2(l);
}

// ---- launch 3: probe dtype + decode indices + degree/count atomics ----
__global__ void k_decode(const int* __restrict__ ei32) {
    int v = ei32[2 * threadIdx.x + 1] | ei32[2 * threadIdx.x + 513];
    int is64 = !__syncthreads_or(v != 0);

    int e = blockIdx.x * blockDim.x + threadIdx.x;
    if (e >= N_EDGES) return;
    int r, c;
    if (is64) {
        r = ei32[2 * e];
        c = ei32[2 * (N_EDGES + e)];
    } else {
        r = ei32[e];
        c = ei32[N_EDGES + e];
    }
    g_row[e] = r;
    g_col[e] = c;
    atomicAdd(&g_deg[c], 1.f);
    atomicAdd(&g_cnt[r], 1.f);
}

// ---- launch 4 (profiled slot): xw = x @ W1 via mma.sync bf16 hi/lo ----
// 384 blocks x 256 thr; 8 warps = 2 row-halves x 4 K-splits; warp tile m16n32.
__global__ void __launch_bounds__(256) k_gemm_mma(const float* __restrict__ x) {
    __shared__ __align__(16) float sred[SPLITS * 32 * 32];   // 16 KB

    const int tid  = threadIdx.x;
    const int wid  = tid >> 5;
    const int lane = tid & 31;
    const int rg   = wid & 1;        // row half (rows rg*16 .. +15)
    const int ks   = wid >> 1;       // K-split 0..3
    const int g    = lane >> 2;      // fragment group 0..7
    const int t    = lane & 3;       // thread-in-group
    const int row0 = blockIdx.x * 32;

    const float* pa = x + (size_t)(row0 + rg * 16 + g) * F_IN;      // row g
    const float* pb = pa + (size_t)8 * F_IN;                        // row g+8

    const int s_beg = ks * SPS;
    const int s_end = min(s_beg + SPS, NKS);

    float acc[4][4];
#pragma unroll
    for (int j = 0; j < 4; j++)
#pragma unroll
        for (int r = 0; r < 4; r++) acc[j][r] = 0.f;

    // A-fragment loader: f[0]=(g,2t) f[1]=(g+8,2t) f[2]=(g,2t+8) f[3]=(g+8,2t+8)
    #define LDA(f, s) { \
        int k0 = (s) * 16 + 2 * t; \
        if (k0 + 10 <= F_IN) { \
            (f)[0] = make_float2(__ldg(pa + k0),     __ldg(pa + k0 + 1)); \
            (f)[1] = make_float2(__ldg(pb + k0),     __ldg(pb + k0 + 1)); \
            (f)[2] = make_float2(__ldg(pa + k0 + 8), __ldg(pa + k0 + 9)); \
            (f)[3] = make_float2(__ldg(pb + k0 + 8), __ldg(pb + k0 + 9)); \
        } else { \
            (f)[0] = make_float2(k0     < F_IN ? __ldg(pa + k0)     : 0.f, \
                                 k0 + 1 < F_IN ? __ldg(pa + k0 + 1) : 0.f); \
            (f)[1] = make_float2(k0     < F_IN ? __ldg(pb + k0)     : 0.f, \
                                 k0 + 1 < F_IN ? __ldg(pb + k0 + 1) : 0.f); \
            (f)[2] = make_float2(k0 + 8 < F_IN ? __ldg(pa + k0 + 8) : 0.f, \
                                 k0 + 9 < F_IN ? __ldg(pa + k0 + 9) : 0.f); \
            (f)[3] = make_float2(k0 + 8 < F_IN ? __ldg(pb + k0 + 8) : 0.f, \
                                 k0 + 9 < F_IN ? __ldg(pb + k0 + 9) : 0.f); \
        } }

    float2 f[4];
    LDA(f, s_beg);

    for (int s = s_beg; s < s_end; s++) {
        // prefetch next kstep's A while this one computes
        float2 fn[4];
        if (s + 1 < s_end) {
            LDA(fn, s + 1);
        } else {
            fn[0] = fn[1] = fn[2] = fn[3] = make_float2(0.f, 0.f);
        }

        // B fragments (L1/L2-resident tables), tp=t and tp=t+4 (+32 uint4)
        const uint4* Bh = g_bfhi + ((s * 8 + t) * 8 + g);
        const uint4* Bl = g_bflo + ((s * 8 + t) * 8 + g);
        uint4 bh0 = __ldg(Bh), bh1 = __ldg(Bh + 32);
        uint4 bl0 = __ldg(Bl), bl1 = __ldg(Bl + 32);

        // convert A to bf16 hi/lo fragments
        unsigned ah[4], al[4];
#pragma unroll
        for (int i = 0; i < 4; i++) {
            __nv_bfloat162 h = __float22bfloat162_rn(f[i]);
            __nv_bfloat162 l = __float22bfloat162_rn(
                make_float2(f[i].x - __bfloat162float(h.x),
                            f[i].y - __bfloat162float(h.y)));
            ah[i] = bits2(h);
            al[i] = bits2(l);
        }

        // 12 MMAs: 4 n-tiles x {hh, lh, hl}
#pragma unroll
        for (int j = 0; j < 4; j++) {
            unsigned bh_lo = (&bh0.x)[j], bh_hi = (&bh1.x)[j];
            unsigned bl_lo = (&bl0.x)[j], bl_hi = (&bl1.x)[j];
            MMA16816(acc[j], ah[0], ah[1], ah[2], ah[3], bh_lo, bh_hi);
            MMA16816(acc[j], al[0], al[1], al[2], al[3], bh_lo, bh_hi);
            MMA16816(acc[j], ah[0], ah[1], ah[2], ah[3], bl_lo, bl_hi);
        }

#pragma unroll
        for (int i = 0; i < 4; i++) f[i] = fn[i];
    }

    // cross-split reduction: sred[ks][row(32)][col(32)]
    {
        float* base = sred + ks * 1024 + (rg * 16 + g) * 32;
#pragma unroll
        for (int j = 0; j < 4; j++) {
            *(float2*)(base + 8 * j + 2 * t)           = make_float2(acc[j][0], acc[j][1]);
            *(float2*)(base + 8 * 32 + 8 * j + 2 * t)  = make_float2(acc[j][2], acc[j][3]);
        }
    }
    __syncthreads();

    // 256 threads x float4: sum 4 split partials, store
    {
        int row = tid >> 3;
        int c4  = (tid & 7) * 4;
        float4 v = *(const float4*)(sred + row * 32 + c4);
#pragma unroll
        for (int k2 = 1; k2 < SPLITS; k2++) {
            float4 b = *(const float4*)(sred + k2 * 1024 + row * 32 + c4);
            v.x += b.x; v.y += b.y; v.z += b.z; v.w += b.w;
        }
        *(float4*)(g_xw + (size_t)(row0 + row) * H1 + c4) = v;
    }
}

// ---- launch 5: zero agg2 (needed before scatter2) ----
__global__ void k_init_b() {
    int i = blockIdx.x * blockDim.x + threadIdx.x;
    if (i < N_NODES * H1) g_agg2[i] = 0.f;
}

// ---- launch 6: GCN scatter: agg1[r] += dis[r]*dis[c]*xw[c], 8 lanes/edge, red.v4 ----
__global__ void k_scatter1() {
    int t = blockIdx.x * blockDim.x + threadIdx.x;
    int e = t >> 3;
    if (e >= N_EDGES) return;
    int g = t & 7;
    int r = g_row[e];
    int c = g_col[e];
    float w = rsqrtf(g_deg[r]) * rsqrtf(g_deg[c]);
    float4 v = *(const float4*)(g_xw + c * H1 + g * 4);
    red4(g_agg1 + r * H1 + g * 4, w * v.x, w * v.y, w * v.z, w * v.w);
}

// ---- launch 7: h = relu(agg1 + selfloop + b1) ----
__global__ void k_hidden(const float* __restrict__ b1) {
    int i = blockIdx.x * blockDim.x + threadIdx.x;
    if (i >= N_NODES * H1) return;
    int node = i >> 5;
    int c    = i & 31;
    float d = rsqrtf(g_deg[node]);
    float v = g_agg1[i] + d * d * g_xw[i] + __ldg(b1 + c);
    g_h[i] = fmaxf(v, 0.f);
}

// ---- launch 8: SAGE scatter: agg2[src] += h[dst], 8 lanes/edge, red.v4 ----
__global__ void k_scatter2() {
    int t = blockIdx.x * blockDim.x + threadIdx.x;
    int e = t >> 3;
    if (e >= N_EDGES) return;
    int g = t & 7;
    int r = g_row[e];
    int c = g_col[e];
    float4 v = *(const float4*)(g_h + c * H1 + g * 4);
    red4(g_agg2 + r * H1 + g * 4, v.x, v.y, v.z, v.w);
}

// ---- launch 9: head ----
__global__ void __launch_bounds__(256) k_head(const float* __restrict__ Wl,
                                              const float* __restrict__ bl,
                                              const float* __restrict__ Wr,
                                              const float* __restrict__ br,
                                              const float* __restrict__ W3,
                                              const float* __restrict__ b3,
                                              float* __restrict__ out) {
    const unsigned FULL = 0xffffffffu;
    int gw   = (blockIdx.x * blockDim.x + threadIdx.x) >> 5;
    int lane = threadIdx.x & 31;
    if (gw >= N_NODES) return;

    float hv = g_h[gw * H1 + lane];
    float av = g_agg2[gw * H1 + lane];
    float cv = g_cnt[gw];
    av = (cv > 0.f) ? av / cv : 0.f;

    float o = 0.f;
    if (lane < H2) o = __ldg(bl + lane) + __ldg(br + lane);
#pragma unroll
    for (int k = 0; k < H1; k++) {
        float hk = __shfl_sync(FULL, hv, k);
        float ak = __shfl_sync(FULL, av, k);
        if (lane < H2)
            o = fmaf(hk, __ldg(Wl + k * H2 + lane),
                fmaf(ak, __ldg(Wr + k * H2 + lane), o));
    }
    o = fmaxf(o, 0.f);

    float ss = o * o;
#pragma unroll
    for (int off = 8; off > 0; off >>= 1) ss += __shfl_xor_sync(FULL, ss, off);
    float inv = 1.f / (sqrtf(ss) + 1e-6f);
    float on  = o * inv;

    float l = (lane < NCLS) ? __ldg(b3 + lane) : -1e30f;
#pragma unroll
    for (int c = 0; c < H2; c++) {
        float oc = __shfl_sync(FULL, on, c);
        if (lane < NCLS) l = fmaf(oc, __ldg(W3 + c * NCLS + lane), l);
    }

    float m = l;
#pragma unroll
    for (int off = 4; off > 0; off >>= 1) m = fmaxf(m, __shfl_xor_sync(FULL, m, off));
    float ev = expf(l - m);
    float sm = ev;
#pragma unroll
    for (int off = 4; off > 0; off >>= 1) sm += __shfl_xor_sync(FULL, sm, off);

    if (lane < NCLS) out[gw * NCLS + lane] = ev / sm;
}

extern "C" void kernel_launch(void* const* d_in, const int* in_sizes, int n_in,
                              void* d_out, int out_size) {
    const float* x  = (const float*)d_in[0];
    const int*   ei = (const int*)d_in[1];
    const float* W1 = (const float*)d_in[2];
    const float* b1 = (const float*)d_in[3];
    const float* Wl = (const float*)d_in[4];
    const float* bl = (const float*)d_in[5];
    const float* Wr = (const float*)d_in[6];
    const float* br = (const float*)d_in[7];
    const float* W3 = (const float*)d_in[8];
    const float* b3 = (const float*)d_in[9];
    float* out = (float*)d_out;

    const int T = 256;
    k_init_a<<<(N_NODES * H1 + T - 1) / T, T>>>();                 // 1
    k_wpack<<<(NKS * 8 * 32 + T - 1) / T, T>>>(W1);                // 2
    k_decode<<<(N_EDGES + T - 1) / T, T>>>(ei);                    // 3
    k_gemm_mma<<<N_NODES / 32, 256>>>(x);                          // 4 (profiled)
    k_init_b<<<(N_NODES * H1 + T - 1) / T, T>>>();                 // 5
    k_scatter1<<<(N_EDGES * 8 + T - 1) / T, T>>>();                // 6
    k_hidden<<<(N_NODES * H1 + T - 1) / T, T>>>(b1);               // 7
    k_scatter2<<<(N_EDGES * 8 + T - 1) / T, T>>>();                // 8
    k_head<<<(N_NODES + 7) / 8, T>>>(Wl, bl, Wr, br, W3, b3, out); // 9
}

// round 16
// speedup vs baseline: 1.0283x; 1.0283x over previous
#include <cuda_runtime.h>
#include <cuda_bf16.h>
#include <math.h>

#define N_NODES 12288
#define N_EDGES 196608
#define F_IN    1433
#define H1      32
#define H2      16
#define NCLS    7

#define NKS     96              // k16 steps incl. zero pad (12 chunks x 8)
#define NCHK    12              // chunks of K=128 per block
#define SPLITS  4               // K-split across warp pairs (ksteps within chunk)
#define XROWB   272             // smem row stride bytes (136 bf16): +4 banks/row
#define SM_LO   8704            // lo tile offset (32 rows * 272)

// ---- scratch (static device globals; no allocation allowed) ----
__device__ float g_xw  [N_NODES * H1];
__device__ float g_h   [N_NODES * H1];
__device__ float g_agg1[N_NODES * H1];
__device__ float g_agg2[N_NODES * H1];
__device__ float g_deg [N_NODES];
__device__ float g_cnt [N_NODES];
__device__ int   g_row [N_EDGES];
__device__ int   g_col [N_EDGES];
// B fragment tables, fragment-ready layout: uint4 index = (kp*8 + g), kp = 8s+tp
__device__ uint4 g_bfhi[NKS * 8 * 8];
__device__ uint4 g_bflo[NKS * 8 * 8];

__device__ __forceinline__ void red4(float* p, float a, float b, float c, float d) {
    asm volatile("red.global.add.v4.f32 [%0], {%1, %2, %3, %4};"
                 :: "l"(p), "f"(a), "f"(b), "f"(c), "f"(d) : "memory");
}

#define MMA16816(c, a0, a1, a2, a3, b0, b1) \
    asm volatile("mma.sync.aligned.m16n8k16.row.col.f32.bf16.bf16.f32 " \
        "{%0,%1,%2,%3}, {%4,%5,%6,%7}, {%8,%9}, {%0,%1,%2,%3};" \
        : "+f"((c)[0]), "+f"((c)[1]), "+f"((c)[2]), "+f"((c)[3]) \
        : "r"(a0), "r"(a1), "r"(a2), "r"(a3), "r"(b0), "r"(b1))

#define LDMX4(r, addr) \
    asm volatile("ldmatrix.sync.aligned.m8n8.x4.shared.b16 {%0,%1,%2,%3}, [%4];" \
        : "=r"((r)[0]), "=r"((r)[1]), "=r"((r)[2]), "=r"((r)[3]) : "r"(addr))

__device__ __forceinline__ unsigned bits2(__nv_bfloat162 v) {
    unsigned u; memcpy(&u, &v, 4); return u;
}

// ---- launch 1: zero agg1/agg2, init deg/cnt ----
__global__ void k_init() {
    int i = blockIdx.x * blockDim.x + threadIdx.x;
    if (i < N_NODES * H1) { g_agg1[i] = 0.f; g_agg2[i] = 0.f; }
    if (i < N_NODES) { g_deg[i] = 1.f; g_cnt[i] = 0.f; }
}

// ---- launch 2: pack W1 into bf16 hi/lo B-fragment tables (zero-padded to NKS) ----
__global__ void k_wpack(const float* __restrict__ W1) {
    int i = blockIdx.x * blockDim.x + threadIdx.x;
    if (i >= NKS * 8 * 32) return;
    int kp  = i >> 5;
    int col = i & 31;
    int k   = 2 * kp;
    float f0 = (k     < F_IN) ? __ldg(W1 + (size_t)k * H1 + col)       : 0.f;
    float f1 = (k + 1 < F_IN) ? __ldg(W1 + (size_t)(k + 1) * H1 + col) : 0.f;
    __nv_bfloat162 h = __float22bfloat162_rn(make_float2(f0, f1));
    __nv_bfloat162 l = __float22bfloat162_rn(
        make_float2(f0 - __bfloat162float(h.x), f1 - __bfloat162float(h.y)));
    int g = col & 7, j = col >> 3;
    int w = (kp * 8 + g) * 4 + j;
    ((unsigned*)g_bfhi)[w] = bits2(h);
    ((unsigned*)g_bflo)[w] = bits2(l);
}

// ---- launch 3: probe dtype + decode indices + degree/count atomics ----
__global__ void k_decode(const int* __restrict__ ei32) {
    int v = ei32[2 * threadIdx.x + 1] | ei32[2 * threadIdx.x + 513];
    int is64 = !__syncthreads_or(v != 0);

    int e = blockIdx.x * blockDim.x + threadIdx.x;
    if (e >= N_EDGES) return;
    int r, c;
    if (is64) {
        r = ei32[2 * e];
        c = ei32[2 * (N_EDGES + e)];
    } else {
        r = ei32[e];
        c = ei32[N_EDGES + e];
    }
    g_row[e] = r;
    g_col[e] = c;
    atomicAdd(&g_deg[c], 1.f);
    atomicAdd(&g_cnt[r], 1.f);
}

// ---- launch 4 (profiled slot): xw = x @ W1 via mma.sync bf16 hi/lo + ldmatrix ----
// 384 blocks x 256 thr; 8 warps = 2 row-halves x 4 kstep-quarters.
// x staged coalesced -> bf16 hi/lo smem tiles -> ldmatrix.x4 fragments.
__global__ void __launch_bounds__(256) k_gemm_mma(const float* __restrict__ x) {
    __shared__ __align__(16) char smem[2 * SM_LO];   // hi | lo tiles; sred aliases

    const int tid  = threadIdx.x;
    const int wid  = tid >> 5;
    const int lane = tid & 31;
    const int rg   = wid & 1;        // row half (rows rg*16 .. +15)
    const int kq   = wid >> 1;       // kstep quarter 0..3 (2 ksteps per chunk)
    const int g    = lane >> 2;      // fragment group 0..7
    const int t    = lane & 3;       // thread-in-group
    const int row0 = blockIdx.x * 32;

    // staging mapping: thread -> rows srow+4p (p=0..7), k pair skl, skl+1
    const int srow = tid >> 6;           // 0..3
    const int skl  = (tid & 63) * 2;     // 0..126, even

    // ldmatrix lane pointer: groups -> (rows 0-7, c0)(rows 8-15, c0)(0-7, c8)(8-15, c8)
    const int lrow = rg * 16 + (lane & 7) + ((lane >> 3) & 1) * 8;
    const int lcol = ((lane >> 4) & 1) * 8;
    const unsigned sb  = (unsigned)__cvta_generic_to_shared(smem);
    const unsigned ahx = sb + (unsigned)(lrow * XROWB + lcol * 2);
    const unsigned alx = ahx + SM_LO;

    float acc[4][4];
#pragma unroll
    for (int j = 0; j < 4; j++)
#pragma unroll
        for (int r = 0; r < 4; r++) acc[j][r] = 0.f;

    // prologue: prefetch chunk 0 (fully in range)
    float2 v[8];
#pragma unroll
    for (int p = 0; p < 8; p++) {
        const float* pp = x + (size_t)(row0 + srow + 4 * p) * F_IN + skl;
        v[p] = make_float2(__ldg(pp), __ldg(pp + 1));
    }

    for (int ch = 0; ch < NCHK; ch++) {
        // commit prefetched chunk: convert to bf16 hi/lo, conflict-free STS.32
#pragma unroll
        for (int p = 0; p < 8; p++) {
            __nv_bfloat162 h = __float22bfloat162_rn(v[p]);
            __nv_bfloat162 l = __float22bfloat162_rn(
                make_float2(v[p].x - __bfloat162float(h.x),
                            v[p].y - __bfloat162float(h.y)));
            unsigned off = (unsigned)((srow + 4 * p) * XROWB + skl * 2);
            *(unsigned*)(smem + off)         = bits2(h);
            *(unsigned*)(smem + SM_LO + off) = bits2(l);
        }
        __syncthreads();

        // prefetch next chunk while this one computes (16 LDG in flight)
        if (ch + 1 < NCHK) {
            const int k0 = (ch + 1) * 128;
#pragma unroll
            for (int p = 0; p < 8; p++) {
                const float* pp = x + (size_t)(row0 + srow + 4 * p) * F_IN + k0 + skl;
                float a = (k0 + skl     < F_IN) ? __ldg(pp)     : 0.f;
                float b = (k0 + skl + 1 < F_IN) ? __ldg(pp + 1) : 0.f;
                v[p] = make_float2(a, b);
            }
        }

        // consume: 2 ksteps for this warp
#pragma unroll
        for (int i = 0; i < 2; i++) {
            const int s_loc = kq * 2 + i;
            const int s     = ch * 8 + s_loc;

            unsigned ah[4], al[4];
            LDMX4(ah, ahx + (unsigned)(s_loc * 32));
            LDMX4(al, alx + (unsigned)(s_loc * 32));

            const uint4* Bh = g_bfhi + ((s * 8 + t) * 8 + g);
            const uint4* Bl = g_bflo + ((s * 8 + t) * 8 + g);
            uint4 bh0 = __ldg(Bh), bh1 = __ldg(Bh + 32);
            uint4 bl0 = __ldg(Bl), bl1 = __ldg(Bl + 32);

#pragma unroll
            for (int j = 0; j < 4; j++) {
                unsigned bh_lo = (&bh0.x)[j], bh_hi = (&bh1.x)[j];
                unsigned bl_lo = (&bl0.x)[j], bl_hi = (&bl1.x)[j];
                MMA16816(acc[j], ah[0], ah[1], ah[2], ah[3], bh_lo, bh_hi);
                MMA16816(acc[j], al[0], al[1], al[2], al[3], bh_lo, bh_hi);
                MMA16816(acc[j], ah[0], ah[1], ah[2], ah[3], bl_lo, bl_hi);
            }
        }
        __syncthreads();
    }

    // cross-quarter reduction: sred[kq][row(32)][col(32)] aliases smem (16KB <= 17KB)
    float* sred = (float*)smem;
    {
        float* base = sred + kq * 1024 + (rg * 16 + g) * 32;
#pragma unroll
        for (int j = 0; j < 4; j++) {
            *(float2*)(base + 8 * j + 2 * t)          = make_float2(acc[j][0], acc[j][1]);
            *(float2*)(base + 8 * 32 + 8 * j + 2 * t) = make_float2(acc[j][2], acc[j][3]);
        }
    }
    __syncthreads();

    // 256 threads x float4: sum 4 partials, store
    {
        int row = tid >> 3;
        int c4  = (tid & 7) * 4;
        float4 o = *(const float4*)(sred + row * 32 + c4);
#pragma unroll
        for (int k2 = 1; k2 < SPLITS; k2++) {
            float4 b = *(const float4*)(sred + k2 * 1024 + row * 32 + c4);
            o.x += b.x; o.y += b.y; o.z += b.z; o.w += b.w;
        }
        *(float4*)(g_xw + (size_t)(row0 + row) * H1 + c4) = o;
    }
}

// ---- launch 5: GCN scatter: agg1[r] += dis[r]*dis[c]*xw[c], 8 lanes/edge, red.v4 ----
__global__ void k_scatter1() {
    int t = blockIdx.x * blockDim.x + threadIdx.x;
    int e = t >> 3;
    if (e >= N_EDGES) return;
    int g = t & 7;
    int r = g_row[e];
    int c = g_col[e];
    float w = rsqrtf(g_deg[r]) * rsqrtf(g_deg[c]);
    float4 v = *(const float4*)(g_xw + c * H1 + g * 4);
    red4(g_agg1 + r * H1 + g * 4, w * v.x, w * v.y, w * v.z, w * v.w);
}

// ---- launch 6: h = relu(agg1 + selfloop + b1) ----
__global__ void k_hidden(const float* __restrict__ b1) {
    int i = blockIdx.x * blockDim.x + threadIdx.x;
    if (i >= N_NODES * H1) return;
    int node = i >> 5;
    int c    = i & 31;
    float d = rsqrtf(g_deg[node]);
    float v = g_agg1[i] + d * d * g_xw[i] + __ldg(b1 + c);
    g_h[i] = fmaxf(v, 0.f);
}

// ---- launch 7: SAGE scatter: agg2[src] += h[dst], 8 lanes/edge, red.v4 ----
__global__ void k_scatter2() {
    int t = blockIdx.x * blockDim.x + threadIdx.x;
    int e = t >> 3;
    if (e >= N_EDGES) return;
    int g = t & 7;
    int r = g_row[e];
    int c = g_col[e];
    float4 v = *(const float4*)(g_h + c * H1 + g * 4);
    red4(g_agg2 + r * H1 + g * 4, v.x, v.y, v.z, v.w);
}

// ---- launch 8: head ----
__global__ void __launch_bounds__(256) k_head(const float* __restrict__ Wl,
                                              const float* __restrict__ bl,
                                              const float* __restrict__ Wr,
                                              const float* __restrict__ br,
                                              const float* __restrict__ W3,
                                              const float* __restrict__ b3,
                                              float* __restrict__ out) {
    const unsigned FULL = 0xffffffffu;
    int gw   = (blockIdx.x * blockDim.x + threadIdx.x) >> 5;
    int lane = threadIdx.x & 31;
    if (gw >= N_NODES) return;

    float hv = g_h[gw * H1 + lane];
    float av = g_agg2[gw * H1 + lane];
    float cv = g_cnt[gw];
    av = (cv > 0.f) ? av / cv : 0.f;

    float o = 0.f;
    if (lane < H2) o = __ldg(bl + lane) + __ldg(br + lane);
#pragma unroll
    for (int k = 0; k < H1; k++) {
        float hk = __shfl_sync(FULL, hv, k);
        float ak = __shfl_sync(FULL, av, k);
        if (lane < H2)
            o = fmaf(hk, __ldg(Wl + k * H2 + lane),
                fmaf(ak, __ldg(Wr + k * H2 + lane), o));
    }
    o = fmaxf(o, 0.f);

    float ss = o * o;
#pragma unroll
    for (int off = 8; off > 0; off >>= 1) ss += __shfl_xor_sync(FULL, ss, off);
    float inv = 1.f / (sqrtf(ss) + 1e-6f);
    float on  = o * inv;

    float l = (lane < NCLS) ? __ldg(b3 + lane) : -1e30f;
#pragma unroll
    for (int c = 0; c < H2; c++) {
        float oc = __shfl_sync(FULL, on, c);
        if (lane < NCLS) l = fmaf(oc, __ldg(W3 + c * NCLS + lane), l);
    }

    float m = l;
#pragma unroll
    for (int off = 4; off > 0; off >>= 1) m = fmaxf(m, __shfl_xor_sync(FULL, m, off));
    float ev = expf(l - m);
    float sm = ev;
#pragma unroll
    for (int off = 4; off > 0; off >>= 1) sm += __shfl_xor_sync(FULL, sm, off);

    if (lane < NCLS) out[gw * NCLS + lane] = ev / sm;
}

extern "C" void kernel_launch(void* const* d_in, const int* in_sizes, int n_in,
                              void* d_out, int out_size) {
    const float* x  = (const float*)d_in[0];
    const int*   ei = (const int*)d_in[1];
    const float* W1 = (const float*)d_in[2];
    const float* b1 = (const float*)d_in[3];
    const float* Wl = (const float*)d_in[4];
    const float* bl = (const float*)d_in[5];
    const float* Wr = (const float*)d_in[6];
    const float* br = (const float*)d_in[7];
    const float* W3 = (const float*)d_in[8];
    const float* b3 = (const float*)d_in[9];
    float* out = (float*)d_out;

    const int T = 256;
    k_init<<<(N_NODES * H1 + T - 1) / T, T>>>();                   // 1
    k_wpack<<<(NKS * 8 * 32 + T - 1) / T, T>>>(W1);                // 2
    k_decode<<<(N_EDGES + T - 1) / T, T>>>(ei);                    // 3
    k_gemm_mma<<<N_NODES / 32, 256>>>(x);                          // 4 (profiled)
    k_scatter1<<<(N_EDGES * 8 + T - 1) / T, T>>>();                // 5
    k_hidden<<<(N_NODES * H1 + T - 1) / T, T>>>(b1);               // 6
    k_scatter2<<<(N_EDGES * 8 + T - 1) / T, T>>>();                // 7
    k_head<<<(N_NODES + 7) / 8, T>>>(Wl, bl, Wr, br, W3, b3, out); // 8
}